// round 2
// baseline (speedup 1.0000x reference)
#include <cuda_runtime.h>

#define THREADS 256

// Shared-memory layout (all strides odd => conflict-free for our lane mappings)
constexpr int SA_STRIDE = 95;               // attn plane: 64 rows, data cols [15,79)
constexpr int SA_SIZE   = 64 * SA_STRIDE;   // 6080
constexpr int SX_STRIDE = 69;               // x plane padded by 2: 68 rows
constexpr int SX_SIZE   = 68 * SX_STRIDE;   // 4692
constexpr int ST_STRIDE = 65;               // tmp plane: 64 rows (unpadded, predicated reads)
constexpr int ST_SIZE   = 64 * ST_STRIDE;   // 4160
constexpr int UNION_SIZE  = (SX_SIZE > ST_SIZE) ? SX_SIZE : ST_SIZE;  // 4692
constexpr int SMEM_FLOATS = SA_SIZE + UNION_SIZE;                     // 10772 -> 43088 B

// ---- packed f32x2 helpers (Blackwell fma.rn.f32x2: 1 issue = 2 FMA lanes) ----
using f32x2 = unsigned long long;

__device__ __forceinline__ f32x2 pack2(float lo, float hi) {
    f32x2 d; asm("mov.b64 %0, {%1, %2};" : "=l"(d) : "f"(lo), "f"(hi)); return d;
}
__device__ __forceinline__ void fma2(f32x2& acc, f32x2 a, f32x2 b) {
    asm("fma.rn.f32x2 %0, %1, %2, %0;" : "+l"(acc) : "l"(a), "l"(b));
}
__device__ __forceinline__ void unpack2(f32x2 d, float& lo, float& hi) {
    asm("mov.b64 {%0, %1}, %2;" : "=f"(lo), "=f"(hi) : "l"(d));
}

// Sliding-window 1D conv sweep over taps [J0,J1). acc2[p] packs outputs (2p, 2p+1).
// ld(i) returns window value v[i]; pv[m] = (v[m], v[m+1]) feeds pair p with tap j=m-2p.
template<int J0, int J1, class LoadF>
__device__ __forceinline__ void sweep(f32x2 acc2[8], const f32x2* w2, LoadF ld)
{
    float vprev = ld(J0);
#pragma unroll
    for (int m = J0; m < J1 + 14; m++) {
        const float vnext = ld(m + 1);
        const f32x2 pv = pack2(vprev, vnext);
        vprev = vnext;
#pragma unroll
        for (int p = 0; p < 8; p++) {
            const int j = m - 2 * p;
            if (j >= J0 && j < J1) fma2(acc2[p], pv, w2[j - J0]);
        }
    }
}

// 1D conv with K taps; splits K>16 into two sweeps to bound live packed-weight regs.
template<int K, class LoadF>
__device__ __forceinline__ void conv1d(f32x2 acc2[8], const float* __restrict__ wg, LoadF ld)
{
    if constexpr (K <= 16) {
        f32x2 w2[K];
#pragma unroll
        for (int j = 0; j < K; j++) { const float w = __ldg(wg + j); w2[j] = pack2(w, w); }
        sweep<0, K>(acc2, w2, ld);
    } else {
        {
            f32x2 w2[16];
#pragma unroll
            for (int j = 0; j < 16; j++) { const float w = __ldg(wg + j); w2[j] = pack2(w, w); }
            sweep<0, 16>(acc2, w2, ld);
        }
        {
            f32x2 w2[K - 16];
#pragma unroll
            for (int j = 16; j < K; j++) { const float w = __ldg(wg + j); w2[j - 16] = pack2(w, w); }
            sweep<16, K>(acc2, w2, ld);
        }
    }
}

// Horizontal 1xK: s_a -> s_t. Thread: row = tid&63, 16 cols from col0.
template<int K>
__device__ __forceinline__ void hbranch(const float* __restrict__ s_a,
                                        float* __restrict__ s_t,
                                        const float* __restrict__ wg,
                                        float bias, int row, int col0)
{
    f32x2 acc2[8];
    const f32x2 bb = pack2(bias, bias);
#pragma unroll
    for (int p = 0; p < 8; p++) acc2[p] = bb;

    const float* sr = s_a + row * SA_STRIDE + 15 + col0 - (K / 2);
    conv1d<K>(acc2, wg, [&](int i) { return sr[i]; });

    float* st = s_t + row * ST_STRIDE + col0;
#pragma unroll
    for (int p = 0; p < 8; p++) {
        float lo, hi; unpack2(acc2[p], lo, hi);
        st[2 * p] = lo; st[2 * p + 1] = hi;
    }
}

// Vertical Kx1: s_t -> global section. Thread: col = tid&63, 16 rows from r0.
template<int K>
__device__ __forceinline__ void vbranch(const float* __restrict__ s_t,
                                        const float* __restrict__ wg,
                                        float bias,
                                        float* __restrict__ osec,
                                        int col, int r0)
{
    f32x2 acc2[8];
    const f32x2 bb = pack2(bias, bias);
#pragma unroll
    for (int p = 0; p < 8; p++) acc2[p] = bb;

    conv1d<K>(acc2, wg, [&](int i) {
        const int ridx = r0 - (K / 2) + i;
        return (ridx >= 0 && ridx < 64) ? s_t[ridx * ST_STRIDE + col] : 0.0f;
    });

#pragma unroll
    for (int p = 0; p < 8; p++) {
        float lo, hi; unpack2(acc2[p], lo, hi);
        osec[(r0 + 2 * p) * 64 + col] = lo;
        osec[(r0 + 2 * p + 1) * 64 + col] = hi;
    }
}

__global__ __launch_bounds__(THREADS, 3)
void lka_kernel(const float* __restrict__ x,
                const float* __restrict__ w0,  const float* __restrict__ b0,
                const float* __restrict__ w01, const float* __restrict__ b01,
                const float* __restrict__ w02, const float* __restrict__ b02,
                const float* __restrict__ w11, const float* __restrict__ b11,
                const float* __restrict__ w12, const float* __restrict__ b12,
                const float* __restrict__ w21, const float* __restrict__ b21,
                const float* __restrict__ w22, const float* __restrict__ b22,
                float* __restrict__ out)
{
    __shared__ float sm[SMEM_FLOATS];
    float* s_a = sm;              // attn plane (lives across all branches)
    float* s_x = sm + SA_SIZE;    // x plane   (dead after 5x5)   } union
    float* s_t = sm + SA_SIZE;    // h-conv tmp (per branch)      } union

    const int tid = threadIdx.x;
    const int bc  = blockIdx.x;        // b*128 + c
    const int c   = bc & 127;
    const int b   = bc >> 7;

    const int row  = tid & 63;
    const int col0 = (tid >> 6) << 4;

    const float* xp = x + (long)bc * 4096;
    float* outb = out + (long)b * (640 * 4096) + (long)c * 4096;

    // Zero all smem (zero padding for s_x borders and s_a side columns)
    for (int i = tid; i < SMEM_FLOATS; i += THREADS) sm[i] = 0.0f;
    __syncthreads();

    // Load x plane (LDG.128) into padded smem; pass-through section 0 (STG.128)
    {
        const float4* xp4 = (const float4*)xp;
        float4* out4 = (float4*)outb;
#pragma unroll
        for (int k = 0; k < 4; k++) {
            const int i4 = tid + k * THREADS;
            const float4 v = xp4[i4];
            out4[i4] = v;
            const int i  = i4 << 2;
            float* dst = &s_x[((i >> 6) + 2) * SX_STRIDE + (i & 63) + 2];
            dst[0] = v.x; dst[1] = v.y; dst[2] = v.z; dst[3] = v.w;
        }
    }
    __syncthreads();

    // 5x5 depthwise conv: s_x -> s_a (includes bias => reference 'attn')
    {
        const float* w0c = w0 + c * 25;
        const float bias = __ldg(b0 + c);
        f32x2 acc2[8];
        const f32x2 bb = pack2(bias, bias);
#pragma unroll
        for (int p = 0; p < 8; p++) acc2[p] = bb;
#pragma unroll
        for (int r = 0; r < 5; r++) {
            const float* sr = s_x + (row + r) * SX_STRIDE + col0;
            f32x2 w2[5];
#pragma unroll
            for (int j = 0; j < 5; j++) {
                const float w = __ldg(w0c + r * 5 + j);
                w2[j] = pack2(w, w);
            }
            sweep<0, 5>(acc2, w2, [&](int i) { return sr[i]; });
        }
        float* sa = s_a + row * SA_STRIDE + 15 + col0;
#pragma unroll
        for (int p = 0; p < 8; p++) {
            float lo, hi; unpack2(acc2[p], lo, hi);
            sa[2 * p] = lo; sa[2 * p + 1] = hi;
        }
    }
    __syncthreads();   // also guards s_x (union with s_t) against hpass writes

    // Section 1: attn, copied from smem with STG.128
    {
        float4* out1 = (float4*)(outb + 128 * 4096);
#pragma unroll
        for (int k = 0; k < 4; k++) {
            const int i4 = tid + k * THREADS;
            const int i  = i4 << 2;
            const float* srow = &s_a[(i >> 6) * SA_STRIDE + 15 + (i & 63)];
            out1[i4] = make_float4(srow[0], srow[1], srow[2], srow[3]);
        }
    }

    // Branch 0: 1x7 then 7x1 -> section 2
    hbranch<7>(s_a, s_t, w01 + c * 7, __ldg(b01 + c), row, col0);
    __syncthreads();
    vbranch<7>(s_t, w02 + c * 7, __ldg(b02 + c), outb + 2 * 128 * 4096, row, col0);
    __syncthreads();

    // Branch 1: 1x15 then 15x1 -> section 3
    hbranch<15>(s_a, s_t, w11 + c * 15, __ldg(b11 + c), row, col0);
    __syncthreads();
    vbranch<15>(s_t, w12 + c * 15, __ldg(b12 + c), outb + 3 * 128 * 4096, row, col0);
    __syncthreads();

    // Branch 2: 1x31 then 31x1 -> section 4
    hbranch<31>(s_a, s_t, w21 + c * 31, __ldg(b21 + c), row, col0);
    __syncthreads();
    vbranch<31>(s_t, w22 + c * 31, __ldg(b22 + c), outb + 4 * 128 * 4096, row, col0);
}

extern "C" void kernel_launch(void* const* d_in, const int* in_sizes, int n_in,
                              void* d_out, int out_size)
{
    lka_kernel<<<32 * 128, THREADS>>>(
        (const float*)d_in[0],
        (const float*)d_in[1],  (const float*)d_in[2],
        (const float*)d_in[3],  (const float*)d_in[4],
        (const float*)d_in[5],  (const float*)d_in[6],
        (const float*)d_in[7],  (const float*)d_in[8],
        (const float*)d_in[9],  (const float*)d_in[10],
        (const float*)d_in[11], (const float*)d_in[12],
        (const float*)d_in[13], (const float*)d_in[14],
        (float*)d_out);
}

// round 3
// speedup vs baseline: 1.0301x; 1.0301x over previous
#include <cuda_runtime.h>

#define THREADS 256

using ull = unsigned long long;

// ---------------- shared memory layout ----------------
constexpr int SAT_STRIDE = 66;                     // s_aT: row = fixed w, 64 h + pad (even => b64 aligned)
constexpr int SAT_ROWS   = 94;                     // w in [-15, 79): 15 zero margin each side
constexpr int SAT_SIZE   = SAT_ROWS * SAT_STRIDE;  // 6204
constexpr int SX_STRIDE  = 69;                     // x plane padded by 2 (odd => conflict-free row reads)
constexpr int SX_SIZE    = 68 * SX_STRIDE;         // 4692
constexpr int ST_STRIDE  = 66;                     // s_t[h][w], even stride for b64 col-pair reads
constexpr int ST_SIZE    = 64 * ST_STRIDE;         // 4224
constexpr int UNION_SIZE = SX_SIZE;                // s_x and s_t share space (4692 > 4224)
constexpr int ZERO_FLOATS = SAT_SIZE + UNION_SIZE; // 10896 (even)
constexpr int W25_OFF   = ZERO_FLOATS;             // 25 floats: 5x5 weights
constexpr int B0_OFF    = W25_OFF + 25;
constexpr int DUP_OFF   = B0_OFF + 1;              // 10922 (even => 8B aligned pairs)
// dup region: 106 weight pairs (order H7,V7,H15,V15,H31,V31) + 6 bias pairs
constexpr int SMEM_FLOATS = DUP_OFF + 224;         // 11146 floats = 44584 B

// ---------------- packed f32x2 helpers ----------------
__device__ __forceinline__ ull ldpair(const float* p) {          // LDS.64, no ALU
    return *(const ull*)p;
}
__device__ __forceinline__ void fma2(ull& acc, ull a, ull b) {   // 1 issue = 2 fp32 FMA lanes
    asm("fma.rn.f32x2 %0, %1, %2, %0;" : "+l"(acc) : "l"(a), "l"(b));
}
__device__ __forceinline__ float2 up2(ull d) {
    float2 r; asm("mov.b64 {%0, %1}, %2;" : "=f"(r.x), "=f"(r.y) : "l"(d)); return r;
}

// Sliding-window conv over taps, chunked 8 at a time to bound live weight regs.
// acc[p]: output index p (p = w-offset for hpass, row-offset for vpass), lanes = the pair dim.
// ld(m) returns the (pair) window value at sliding index m; tap j feeds acc[p] at m = p + j.
template<int K, int C0, class LD>
__device__ __forceinline__ void conv_chunks(ull acc[8], const float* __restrict__ dupw, LD ld)
{
    constexpr int C1 = (C0 + 8 < K) ? (C0 + 8) : K;
    ull w2[C1 - C0];
#pragma unroll
    for (int t = 0; t < C1 - C0; t++) w2[t] = ldpair(dupw + 2 * (C0 + t));  // broadcast LDS.64
#pragma unroll
    for (int m = C0; m < C1 + 7; m++) {
        const ull vv = ld(m);
#pragma unroll
        for (int p = 0; p < 8; p++) {
            const int j = m - p;
            if (j >= C0 && j < C1) fma2(acc[p], vv, w2[j - C0]);
        }
    }
    if constexpr (C1 < K) conv_chunks<K, C1>(acc, dupw, ld);
}

// Horizontal 1xK: s_aT -> s_t. Thread: h-pair (2(tid&31), +1), 8 w's from 8*(tid>>5).
// Window loads: s_aT[widx][h0..h0+1] contiguous b64, warp-contiguous (conflict-free).
template<int K>
__device__ __forceinline__ void hbranch(const float* __restrict__ s_aT,
                                        float* __restrict__ s_t,
                                        const float* __restrict__ dupw,
                                        ull bias2, int tid)
{
    const int h0 = (tid & 31) * 2;
    const int w0 = (tid >> 5) * 8;
    ull acc[8];
#pragma unroll
    for (int p = 0; p < 8; p++) acc[p] = bias2;
    const float* base = s_aT + (w0 - K / 2 + 15) * SAT_STRIDE + h0;
    conv_chunks<K, 0>(acc, dupw, [&](int m) { return ldpair(base + m * SAT_STRIDE); });
#pragma unroll
    for (int p = 0; p < 8; p++) {
        const float2 v = up2(acc[p]);
        s_t[h0 * ST_STRIDE + w0 + p] = v.x;
        s_t[(h0 + 1) * ST_STRIDE + w0 + p] = v.y;
    }
}

// Vertical Kx1: s_t -> global. Thread: col-pair (2(tid&31), +1), 8 rows from 8*(tid>>5).
// Window loads: s_t[hidx][w0..w0+1] contiguous b64; zero padding via predication.
template<int K>
__device__ __forceinline__ void vbranch(const float* __restrict__ s_t,
                                        const float* __restrict__ dupw,
                                        ull bias2,
                                        float* __restrict__ osec, int tid)
{
    const int w0 = (tid & 31) * 2;
    const int r0 = (tid >> 5) * 8;
    ull acc[8];
#pragma unroll
    for (int p = 0; p < 8; p++) acc[p] = bias2;
    conv_chunks<K, 0>(acc, dupw, [&](int m) {
        const int hidx = r0 - K / 2 + m;
        ull vv = 0ull;
        if ((unsigned)hidx < 64u) vv = ldpair(s_t + hidx * ST_STRIDE + w0);
        return vv;
    });
#pragma unroll
    for (int p = 0; p < 8; p++) {
        const float2 v = up2(acc[p]);
        *(float2*)&osec[(r0 + p) * 64 + w0] = v;   // STG.64, warp-coalesced
    }
}

__global__ __launch_bounds__(THREADS, 4)
void lka_kernel(const float* __restrict__ x,
                const float* __restrict__ w0,  const float* __restrict__ b0,
                const float* __restrict__ w01, const float* __restrict__ b01,
                const float* __restrict__ w02, const float* __restrict__ b02,
                const float* __restrict__ w11, const float* __restrict__ b11,
                const float* __restrict__ w12, const float* __restrict__ b12,
                const float* __restrict__ w21, const float* __restrict__ b21,
                const float* __restrict__ w22, const float* __restrict__ b22,
                float* __restrict__ out)
{
    __shared__ float sm[SMEM_FLOATS];
    float* s_aT = sm;              // transposed attn plane (lives across branches)
    float* s_x  = sm + SAT_SIZE;   // x plane (dead after 5x5)     } union
    float* s_t  = sm + SAT_SIZE;   // h-conv tmp [h][w]            } union
    const float* dup = sm + DUP_OFF;

    const int tid = threadIdx.x;
    const int bc  = blockIdx.x;    // b*128 + c
    const int c   = bc & 127;
    const int b   = bc >> 7;

    const float* xp = x + (long)bc * 4096;
    float* outb = out + (long)b * (640 * 4096) + (long)c * 4096;

    // Zero data region (provides zero margins for s_aT and s_x borders)
    for (int i = tid; i < ZERO_FLOATS; i += THREADS) sm[i] = 0.0f;

    // Build per-channel weight tables (disjoint from zeroed region)
    if (tid < 112) {
        float v;
        const int j = tid;
        if (j < 7)        v = __ldg(w01 + c * 7  + j);
        else if (j < 14)  v = __ldg(w02 + c * 7  + j - 7);
        else if (j < 29)  v = __ldg(w11 + c * 15 + j - 14);
        else if (j < 44)  v = __ldg(w12 + c * 15 + j - 29);
        else if (j < 75)  v = __ldg(w21 + c * 31 + j - 44);
        else if (j < 106) v = __ldg(w22 + c * 31 + j - 75);
        else {
            const float* bp = (j == 106) ? b01 : (j == 107) ? b02 : (j == 108) ? b11
                            : (j == 109) ? b12 : (j == 110) ? b21 : b22;
            v = __ldg(bp + c);
        }
        sm[DUP_OFF + 2 * j]     = v;
        sm[DUP_OFF + 2 * j + 1] = v;
    } else if (tid < 137) {
        sm[W25_OFF + tid - 112] = __ldg(w0 + c * 25 + (tid - 112));
    } else if (tid == 137) {
        sm[B0_OFF] = __ldg(b0 + c);
    }
    __syncthreads();

    // Load x plane (LDG.128) into padded s_x; pass-through section 0 (STG.128)
    {
        const float4* xp4 = (const float4*)xp;
        float4* out4 = (float4*)outb;
#pragma unroll
        for (int k = 0; k < 4; k++) {
            const int i4 = tid + k * THREADS;
            const float4 v = xp4[i4];
            out4[i4] = v;
            const int i = i4 << 2;
            float* dst = &s_x[((i >> 6) + 2) * SX_STRIDE + (i & 63) + 2];
            dst[0] = v.x; dst[1] = v.y; dst[2] = v.z; dst[3] = v.w;
        }
    }
    __syncthreads();

    // 5x5 depthwise conv (scalar): s_x -> s_aT (transposed write, lane-contiguous)
    {
        float w[25];
#pragma unroll
        for (int j = 0; j < 25; j++) w[j] = sm[W25_OFF + j];  // LDS broadcast
        const float bias = sm[B0_OFF];
        const int h    = tid & 63;
        const int col0 = (tid >> 6) << 4;
        float acc[16];
#pragma unroll
        for (int o = 0; o < 16; o++) acc[o] = bias;
#pragma unroll
        for (int r = 0; r < 5; r++) {
            const float* srow = s_x + (h + r) * SX_STRIDE + col0;
#pragma unroll
            for (int i = 0; i < 20; i++) {
                const float v = srow[i];
#pragma unroll
                for (int o = 0; o < 16; o++) {
                    const int j = i - o;
                    if (j >= 0 && j < 5) acc[o] = fmaf(v, w[r * 5 + j], acc[o]);
                }
            }
        }
#pragma unroll
        for (int o = 0; o < 16; o++)
            s_aT[(col0 + o + 15) * SAT_STRIDE + h] = acc[o];
    }
    __syncthreads();

    // Section 1: attn, read from s_aT (2-way conflict), coalesced STG.32
    {
        float* out1 = outb + 128 * 4096;
        const int wq  = tid & 63;
        const int hq0 = (tid >> 6) * 16;
#pragma unroll
        for (int t = 0; t < 16; t++)
            out1[(hq0 + t) * 64 + wq] = s_aT[(wq + 15) * SAT_STRIDE + hq0 + t];
    }

    // Branch 0: 1x7 then 7x1 -> section 2
    hbranch<7>(s_aT, s_t, dup + 0,   ldpair(dup + 212), tid);
    __syncthreads();
    vbranch<7>(s_t, dup + 14,  ldpair(dup + 214), outb + 2 * 128 * 4096, tid);
    __syncthreads();

    // Branch 1: 1x15 then 15x1 -> section 3
    hbranch<15>(s_aT, s_t, dup + 28,  ldpair(dup + 216), tid);
    __syncthreads();
    vbranch<15>(s_t, dup + 58,  ldpair(dup + 218), outb + 3 * 128 * 4096, tid);
    __syncthreads();

    // Branch 2: 1x31 then 31x1 -> section 4
    hbranch<31>(s_aT, s_t, dup + 88,  ldpair(dup + 220), tid);
    __syncthreads();
    vbranch<31>(s_t, dup + 150, ldpair(dup + 222), outb + 4 * 128 * 4096, tid);
}

extern "C" void kernel_launch(void* const* d_in, const int* in_sizes, int n_in,
                              void* d_out, int out_size)
{
    lka_kernel<<<32 * 128, THREADS>>>(
        (const float*)d_in[0],
        (const float*)d_in[1],  (const float*)d_in[2],
        (const float*)d_in[3],  (const float*)d_in[4],
        (const float*)d_in[5],  (const float*)d_in[6],
        (const float*)d_in[7],  (const float*)d_in[8],
        (const float*)d_in[9],  (const float*)d_in[10],
        (const float*)d_in[11], (const float*)d_in[12],
        (const float*)d_in[13], (const float*)d_in[14],
        (float*)d_out);
}

// round 4
// speedup vs baseline: 1.0694x; 1.0382x over previous
#include <cuda_runtime.h>

#define THREADS 256
using ull = unsigned long long;

// ---- all-odd strides => every LDS/STS in the kernel is bank-conflict-free ----
constexpr int SA_STRIDE = 95, SA_SIZE = 64 * 95;   // attn plane, data cols [15,79)
constexpr int SX_STRIDE = 69, SX_SIZE = 68 * 69;   // x plane, pad 2 (data cols [2,66))
constexpr int ST_STRIDE = 65, ST_SIZE = 64 * 65;   // h-conv tmp (union with s_x)
constexpr int UNION_SIZE  = SX_SIZE;               // 4692 > 4160
constexpr int DATA_FLOATS = SA_SIZE + UNION_SIZE;  // 10772 (even => tables 8B-aligned)
constexpr int P5_OFF = DATA_FLOATS;                // 5 rows x 6 shifted pairs = 60 floats
constexpr int PB_OFF = P5_OFF + 60;                // branch pair tables: 112 pairs = 224 floats
constexpr int BB_OFF = PB_OFF + 224;               // 7 bias pairs = 14 floats
constexpr int SMEM_FLOATS = BB_OFF + 14;           // 11070 floats = 44280 B (occ 4 OK)

// pair-table float offsets within PB: H7=0, V7=16, H15=32, V15=64, H31=96, V31=160

__device__ __forceinline__ ull ldpair(const float* p) { return *(const ull*)p; }
__device__ __forceinline__ void fma2(ull& acc, ull a, ull b) {
    asm("fma.rn.f32x2 %0, %1, %2, %0;" : "+l"(acc) : "l"(a), "l"(b));
}
__device__ __forceinline__ float2 up2(ull d) {
    float2 r; asm("mov.b64 {%0, %1}, %2;" : "=f"(r.x), "=f"(r.y) : "l"(d)); return r;
}
__device__ __forceinline__ ull dup(float v) {
    ull d; asm("mov.b64 %0, {%1, %1};" : "=l"(d) : "f"(v)); return d;
}

// 16 outputs (8 adjacent pairs) per thread, single streaming window pass.
// acc2[q] = (out_{2q}, out_{2q+1}). Scalar window value v_m (CF 4B LDS), duplicated,
// hits pair q with shifted weight pair P[t] = (w_t, w_{t-1}), t = m-2q in [0,K].
// Rotating 16-slot pair buffer: P[m] loaded at step m, dead after step m+14.
template<int K, class LD>
__device__ __forceinline__ void conv16(ull acc2[8], const float* __restrict__ ptab, LD ld)
{
    ull wb[16];
#pragma unroll
    for (int m = 0; m < K + 15; m++) {
        if (m <= K) wb[m & 15] = ldpair(ptab + 2 * m);   // broadcast LDS.64
        const ull vv = dup(ld(m));
#pragma unroll
        for (int q = 0; q < 8; q++) {
            const int t = m - 2 * q;
            if (t >= 0 && t <= K) fma2(acc2[q], vv, wb[t & 15]);
        }
    }
}

// Horizontal 1xK: s_a -> s_t. Thread: row h = tid&63, 16 cols from col0. All CF.
template<int K>
__device__ __forceinline__ void hbranch(const float* __restrict__ s_a,
                                        float* __restrict__ s_t,
                                        const float* __restrict__ ptab,
                                        ull bias2, int h, int col0)
{
    ull acc2[8];
#pragma unroll
    for (int q = 0; q < 8; q++) acc2[q] = bias2;
    const float* sr = s_a + h * SA_STRIDE + 15 + col0 - K / 2;
    conv16<K>(acc2, ptab, [&](int m) { return sr[m]; });
    float* st = s_t + h * ST_STRIDE + col0;
#pragma unroll
    for (int q = 0; q < 8; q++) {
        const float2 v = up2(acc2[q]);
        st[2 * q] = v.x; st[2 * q + 1] = v.y;
    }
}

// Vertical Kx1: s_t -> global. Thread: col = tid&63, 16 rows from r0. All CF.
template<int K>
__device__ __forceinline__ void vbranch(const float* __restrict__ s_t,
                                        const float* __restrict__ ptab,
                                        ull bias2,
                                        float* __restrict__ osec, int col, int r0)
{
    ull acc2[8];
#pragma unroll
    for (int q = 0; q < 8; q++) acc2[q] = bias2;
    conv16<K>(acc2, ptab, [&](int m) {
        const int ridx = r0 - K / 2 + m;
        return ((unsigned)ridx < 64u) ? s_t[ridx * ST_STRIDE + col] : 0.0f;
    });
#pragma unroll
    for (int q = 0; q < 8; q++) {
        const float2 v = up2(acc2[q]);
        osec[(r0 + 2 * q) * 64 + col] = v.x;
        osec[(r0 + 2 * q + 1) * 64 + col] = v.y;
    }
}

__global__ __launch_bounds__(THREADS, 4)
void lka_kernel(const float* __restrict__ x,
                const float* __restrict__ w0,  const float* __restrict__ b0,
                const float* __restrict__ w01, const float* __restrict__ b01,
                const float* __restrict__ w02, const float* __restrict__ b02,
                const float* __restrict__ w11, const float* __restrict__ b11,
                const float* __restrict__ w12, const float* __restrict__ b12,
                const float* __restrict__ w21, const float* __restrict__ b21,
                const float* __restrict__ w22, const float* __restrict__ b22,
                float* __restrict__ out)
{
    __shared__ float sm[SMEM_FLOATS];
    float* s_a = sm;
    float* s_x = sm + SA_SIZE;   // union
    float* s_t = sm + SA_SIZE;   // union

    const int tid = threadIdx.x;
    const int bc  = blockIdx.x;
    const int c   = bc & 127;
    const int b   = bc >> 7;

    const int h    = tid & 63;
    const int col0 = (tid >> 6) << 4;

    const float* xp = x + (long)bc * 4096;
    float* outb = out + (long)b * (640 * 4096) + (long)c * 4096;

    // ---- targeted zeroing (margins only, ~2.6K floats instead of 10.8K) ----
    for (int i = tid; i < 2048; i += THREADS) {          // s_a cols [0,16) U [79,95)
        const int r = i >> 5, m = i & 31;
        s_a[r * SA_STRIDE + (m < 16 ? m : 63 + m)] = 0.0f;
    }
    for (int i = tid; i < 276; i += THREADS) {           // s_x rows {0,1,66,67}
        const int r = i / 69, cc = i % 69;
        s_x[(r < 2 ? r : 64 + r) * SX_STRIDE + cc] = 0.0f;
    }
    for (int i = tid; i < 320; i += THREADS) {           // s_x cols {0,1,66,67,68}, rows [2,66)
        const int r = 2 + i / 5, cc5 = i % 5;
        s_x[r * SX_STRIDE + (cc5 < 2 ? cc5 : 64 + cc5)] = 0.0f;
    }

    // ---- weight pair tables: P[t] = (w_t, w_{t-1}) ----
    if (tid < 112) {
        int t; int K; const float* w;
        if (tid < 8)       { t = tid;      K = 7;  w = w01 + c * 7;  }
        else if (tid < 16) { t = tid - 8;  K = 7;  w = w02 + c * 7;  }
        else if (tid < 32) { t = tid - 16; K = 15; w = w11 + c * 15; }
        else if (tid < 48) { t = tid - 32; K = 15; w = w12 + c * 15; }
        else if (tid < 80) { t = tid - 48; K = 31; w = w21 + c * 31; }
        else               { t = tid - 80; K = 31; w = w22 + c * 31; }
        sm[PB_OFF + 2 * tid]     = (t < K) ? __ldg(w + t)     : 0.0f;
        sm[PB_OFF + 2 * tid + 1] = (t > 0) ? __ldg(w + t - 1) : 0.0f;
    } else if (tid < 142) {                               // 5x5: 5 rows x 6 pairs
        const int j = tid - 112, r = j / 6, t = j % 6;
        const float* w = w0 + c * 25 + r * 5;
        sm[P5_OFF + 2 * j]     = (t < 5) ? __ldg(w + t)     : 0.0f;
        sm[P5_OFF + 2 * j + 1] = (t > 0) ? __ldg(w + t - 1) : 0.0f;
    } else if (tid < 149) {                               // bias pairs
        const int j = tid - 142;
        const float* bp = (j == 0) ? b0 : (j == 1) ? b01 : (j == 2) ? b02
                        : (j == 3) ? b11 : (j == 4) ? b12 : (j == 5) ? b21 : b22;
        const float v = __ldg(bp + c);
        sm[BB_OFF + 2 * j] = v; sm[BB_OFF + 2 * j + 1] = v;
    }
    __syncthreads();

    // ---- x plane: scalar fill (CF STS) + pass-through section 0 ----
#pragma unroll
    for (int k = 0; k < 16; k++) {
        const int i = tid + k * THREADS;
        const float v = xp[i];
        outb[i] = v;
        s_x[((i >> 6) + 2) * SX_STRIDE + (i & 63) + 2] = v;
    }
    __syncthreads();

    // ---- 5x5 depthwise conv: s_x -> s_a (paired outputs, dup-v trick) ----
    {
        ull acc2[8];
        const ull bias2 = ldpair(sm + BB_OFF);
#pragma unroll
        for (int q = 0; q < 8; q++) acc2[q] = bias2;
#pragma unroll
        for (int r = 0; r < 5; r++) {
            const float* srow = s_x + (h + r) * SX_STRIDE + col0;
            conv16<5>(acc2, sm + P5_OFF + r * 12, [&](int m) { return srow[m]; });
        }
        float* sa = s_a + h * SA_STRIDE + 15 + col0;
#pragma unroll
        for (int q = 0; q < 8; q++) {
            const float2 v = up2(acc2[q]);
            sa[2 * q] = v.x; sa[2 * q + 1] = v.y;
        }
    }
    __syncthreads();

    // ---- section 1: attn copy (CF LDS, coalesced STG) ----
    {
        float* out1 = outb + 128 * 4096;
#pragma unroll
        for (int k = 0; k < 16; k++) {
            const int i = tid + k * THREADS;
            out1[i] = s_a[(i >> 6) * SA_STRIDE + 15 + (i & 63)];
        }
    }

    const float* PB = sm + PB_OFF;
    const float* BB = sm + BB_OFF;

    // ---- branch 0: 1x7 then 7x1 -> section 2 ----
    hbranch<7>(s_a, s_t, PB + 0,   ldpair(BB + 2), h, col0);
    __syncthreads();
    vbranch<7>(s_t, PB + 16,  ldpair(BB + 4), outb + 2 * 128 * 4096, h, col0);
    __syncthreads();

    // ---- branch 1: 1x15 then 15x1 -> section 3 ----
    hbranch<15>(s_a, s_t, PB + 32,  ldpair(BB + 6), h, col0);
    __syncthreads();
    vbranch<15>(s_t, PB + 64,  ldpair(BB + 8), outb + 3 * 128 * 4096, h, col0);
    __syncthreads();

    // ---- branch 2: 1x31 then 31x1 -> section 4 ----
    hbranch<31>(s_a, s_t, PB + 96,  ldpair(BB + 10), h, col0);
    __syncthreads();
    vbranch<31>(s_t, PB + 160, ldpair(BB + 12), outb + 4 * 128 * 4096, h, col0);
}

extern "C" void kernel_launch(void* const* d_in, const int* in_sizes, int n_in,
                              void* d_out, int out_size)
{
    lka_kernel<<<32 * 128, THREADS>>>(
        (const float*)d_in[0],
        (const float*)d_in[1],  (const float*)d_in[2],
        (const float*)d_in[3],  (const float*)d_in[4],
        (const float*)d_in[5],  (const float*)d_in[6],
        (const float*)d_in[7],  (const float*)d_in[8],
        (const float*)d_in[9],  (const float*)d_in[10],
        (const float*)d_in[11], (const float*)d_in[12],
        (const float*)d_in[13], (const float*)d_in[14],
        (float*)d_out);
}

// round 5
// speedup vs baseline: 1.1226x; 1.0497x over previous
#include <cuda_runtime.h>

#define THREADS 256
using ull = unsigned long long;

// ---- all-odd data strides => every window/store LDS/STS is bank-conflict-free ----
constexpr int SA_STRIDE = 95, SA_SIZE = 64 * 95;   // attn plane, data cols [15,79)
constexpr int SX_STRIDE = 69, SX_SIZE = 68 * 69;   // x plane, pad 2 (data cols [2,66))
constexpr int ST_STRIDE = 65, ST_SIZE = 64 * 65;   // h-conv tmp (union with s_x)
constexpr int UNION_SIZE  = SX_SIZE;               // 4692 > 4160
constexpr int DATA_FLOATS = SA_SIZE + UNION_SIZE;  // 10772 (mult of 4 => tables 16B-aligned)
constexpr int P5_OFF = DATA_FLOATS;                // 5 rows x 6 shifted pairs = 60 floats
constexpr int PB_OFF = P5_OFF + 60;                // branch pair tables: 112 pairs = 224 floats
constexpr int BB_OFF = PB_OFF + 224;               // 7 bias pairs = 14 floats
constexpr int SMEM_FLOATS = BB_OFF + 14;           // 11070 floats = 44280 B (occ 4 OK)

// pair-table float offsets within PB: H7=0, V7=16, H15=32, V15=64, H31=96, V31=160

__device__ __forceinline__ ull ldpair(const float* p) { return *(const ull*)p; }
__device__ __forceinline__ void fma2(ull& acc, ull a, ull b) {
    asm("fma.rn.f32x2 %0, %1, %2, %0;" : "+l"(acc) : "l"(a), "l"(b));
}
__device__ __forceinline__ float2 up2(ull d) {
    float2 r; asm("mov.b64 {%0, %1}, %2;" : "=f"(r.x), "=f"(r.y) : "l"(d)); return r;
}
__device__ __forceinline__ ull dup(float v) {
    ull d; asm("mov.b64 %0, {%1, %1};" : "=l"(d) : "f"(v)); return d;
}

// Preload NP weight pairs (NP even) with LDS.128: 2 pairs per wavefront.
template<int NP>
__device__ __forceinline__ void loadpairs(ull* w2, const float* __restrict__ ptab) {
#pragma unroll
    for (int t = 0; t < NP; t += 2) {
        const ulonglong2 p = *(const ulonglong2*)(ptab + 2 * t);
        w2[t] = p.x; w2[t + 1] = p.y;
    }
}

// 16 outputs (8 adjacent pairs), weights fully register-resident (NP pairs).
// acc2[q] = (out_{2q}, out_{2q+1}); tap pair t feeds q at window step m = t + 2q.
template<int NP, class LD>
__device__ __forceinline__ void conv16_reg(ull acc2[8], const ull* w2, LD ld)
{
#pragma unroll
    for (int m = 0; m < NP + 14; m++) {
        const ull vv = dup(ld(m));
#pragma unroll
        for (int q = 0; q < 8; q++) {
            const int t = m - 2 * q;
            if (t >= 0 && t < NP) fma2(acc2[q], vv, w2[t]);
        }
    }
}

// K=31 (NP=32): rotating 16-slot pair buffer, refilled 2 pairs per LDS.128.
// Slot liveness: pair t last used at step t+14; overwritten at t+15/t+16 => safe.
template<class LD>
__device__ __forceinline__ void conv16_rot32(ull acc2[8], const float* __restrict__ ptab, LD ld)
{
    ull wb[16];
#pragma unroll
    for (int m = 0; m < 46; m++) {
        if (m < 32 && !(m & 1)) {
            const ulonglong2 p = *(const ulonglong2*)(ptab + 2 * m);
            wb[m & 15] = p.x; wb[(m + 1) & 15] = p.y;
        }
        const ull vv = dup(ld(m));
#pragma unroll
        for (int q = 0; q < 8; q++) {
            const int t = m - 2 * q;
            if (t >= 0 && t < 32) fma2(acc2[q], vv, wb[t & 15]);
        }
    }
}

template<int K, class LD>
__device__ __forceinline__ void runconv(ull acc2[8], const float* __restrict__ ptab, LD ld)
{
    if constexpr (K == 31) {
        conv16_rot32(acc2, ptab, ld);
    } else {
        ull w2[K + 1];
        loadpairs<K + 1>(w2, ptab);
        conv16_reg<K + 1>(acc2, w2, ld);
    }
}

// Horizontal 1xK: s_a -> s_t. Thread: row h, 16 cols from col0. All CF.
template<int K>
__device__ __forceinline__ void hbranch(const float* __restrict__ s_a,
                                        float* __restrict__ s_t,
                                        const float* __restrict__ ptab,
                                        ull bias2, int h, int col0)
{
    ull acc2[8];
#pragma unroll
    for (int q = 0; q < 8; q++) acc2[q] = bias2;
    const float* sr = s_a + h * SA_STRIDE + 15 + col0 - K / 2;
    runconv<K>(acc2, ptab, [&](int m) { return sr[m]; });
    float* st = s_t + h * ST_STRIDE + col0;
#pragma unroll
    for (int q = 0; q < 8; q++) {
        const float2 v = up2(acc2[q]);
        st[2 * q] = v.x; st[2 * q + 1] = v.y;
    }
}

// Vertical Kx1: s_t -> global. Thread: col, 16 rows from r0. All CF, coalesced STG.
template<int K>
__device__ __forceinline__ void vbranch(const float* __restrict__ s_t,
                                        const float* __restrict__ ptab,
                                        ull bias2,
                                        float* __restrict__ osec, int col, int r0)
{
    ull acc2[8];
#pragma unroll
    for (int q = 0; q < 8; q++) acc2[q] = bias2;
    runconv<K>(acc2, ptab, [&](int m) {
        const int ridx = r0 - K / 2 + m;
        return ((unsigned)ridx < 64u) ? s_t[ridx * ST_STRIDE + col] : 0.0f;
    });
#pragma unroll
    for (int q = 0; q < 8; q++) {
        const float2 v = up2(acc2[q]);
        osec[(r0 + 2 * q) * 64 + col] = v.x;
        osec[(r0 + 2 * q + 1) * 64 + col] = v.y;
    }
}

__global__ __launch_bounds__(THREADS, 4)
void lka_kernel(const float* __restrict__ x,
                const float* __restrict__ w0,  const float* __restrict__ b0,
                const float* __restrict__ w01, const float* __restrict__ b01,
                const float* __restrict__ w02, const float* __restrict__ b02,
                const float* __restrict__ w11, const float* __restrict__ b11,
                const float* __restrict__ w12, const float* __restrict__ b12,
                const float* __restrict__ w21, const float* __restrict__ b21,
                const float* __restrict__ w22, const float* __restrict__ b22,
                float* __restrict__ out)
{
    __shared__ __align__(16) float sm[SMEM_FLOATS];
    float* s_a = sm;
    float* s_x = sm + SA_SIZE;   // union
    float* s_t = sm + SA_SIZE;   // union

    const int tid = threadIdx.x;
    const int bc  = blockIdx.x;
    const int c   = bc & 127;
    const int b   = bc >> 7;

    const int h    = tid & 63;
    const int col0 = (tid >> 6) << 4;

    const float* xp = x + (long)bc * 4096;
    float* outb = out + (long)b * (640 * 4096) + (long)c * 4096;

    // ---- targeted zeroing (margins only) ----
    for (int i = tid; i < 2048; i += THREADS) {          // s_a cols [0,16) U [79,95)
        const int r = i >> 5, m = i & 31;
        s_a[r * SA_STRIDE + (m < 16 ? m : 63 + m)] = 0.0f;
    }
    for (int i = tid; i < 276; i += THREADS) {           // s_x rows {0,1,66,67}
        const int r = i / 69, cc = i % 69;
        s_x[(r < 2 ? r : 64 + r) * SX_STRIDE + cc] = 0.0f;
    }
    for (int i = tid; i < 320; i += THREADS) {           // s_x cols {0,1,66,67,68}, rows [2,66)
        const int r = 2 + i / 5, cc5 = i % 5;
        s_x[r * SX_STRIDE + (cc5 < 2 ? cc5 : 64 + cc5)] = 0.0f;
    }

    // ---- weight pair tables: P[t] = (w_t, w_{t-1}) ----
    if (tid < 112) {
        int t; int K; const float* w;
        if (tid < 8)       { t = tid;      K = 7;  w = w01 + c * 7;  }
        else if (tid < 16) { t = tid - 8;  K = 7;  w = w02 + c * 7;  }
        else if (tid < 32) { t = tid - 16; K = 15; w = w11 + c * 15; }
        else if (tid < 48) { t = tid - 32; K = 15; w = w12 + c * 15; }
        else if (tid < 80) { t = tid - 48; K = 31; w = w21 + c * 31; }
        else               { t = tid - 80; K = 31; w = w22 + c * 31; }
        sm[PB_OFF + 2 * tid]     = (t < K) ? __ldg(w + t)     : 0.0f;
        sm[PB_OFF + 2 * tid + 1] = (t > 0) ? __ldg(w + t - 1) : 0.0f;
    } else if (tid < 142) {                               // 5x5: 5 rows x 6 pairs
        const int j = tid - 112, r = j / 6, t = j % 6;
        const float* w = w0 + c * 25 + r * 5;
        sm[P5_OFF + 2 * j]     = (t < 5) ? __ldg(w + t)     : 0.0f;
        sm[P5_OFF + 2 * j + 1] = (t > 0) ? __ldg(w + t - 1) : 0.0f;
    } else if (tid < 149) {                               // bias pairs
        const int j = tid - 142;
        const float* bp = (j == 0) ? b0 : (j == 1) ? b01 : (j == 2) ? b02
                        : (j == 3) ? b11 : (j == 4) ? b12 : (j == 5) ? b21 : b22;
        const float v = __ldg(bp + c);
        sm[BB_OFF + 2 * j] = v; sm[BB_OFF + 2 * j + 1] = v;
    }
    __syncthreads();

    // ---- x plane: LDG.128 + STG.128 passthrough, scalar CF STS fill ----
    {
        const float4* xp4 = (const float4*)xp;
        float4* out4 = (float4*)outb;
#pragma unroll
        for (int k = 0; k < 4; k++) {
            const int i4 = tid + k * THREADS;
            const float4 v = xp4[i4];
            out4[i4] = v;
            const int i = i4 << 2;
            float* dst = &s_x[((i >> 6) + 2) * SX_STRIDE + (i & 63) + 2];
            dst[0] = v.x; dst[1] = v.y; dst[2] = v.z; dst[3] = v.w;
        }
    }
    __syncthreads();

    // ---- 5x5 depthwise conv: s_x -> s_a (row-wise, register weight pairs) ----
    {
        ull acc2[8];
        const ull bias2 = ldpair(sm + BB_OFF);
#pragma unroll
        for (int q = 0; q < 8; q++) acc2[q] = bias2;
#pragma unroll
        for (int r = 0; r < 5; r++) {
            const float* srow = s_x + (h + r) * SX_STRIDE + col0;
            ull w2[6];
            loadpairs<6>(w2, sm + P5_OFF + r * 12);
            conv16_reg<6>(acc2, w2, [&](int m) { return srow[m]; });
        }
        float* sa = s_a + h * SA_STRIDE + 15 + col0;
#pragma unroll
        for (int q = 0; q < 8; q++) {
            const float2 v = up2(acc2[q]);
            sa[2 * q] = v.x; sa[2 * q + 1] = v.y;
        }
    }
    __syncthreads();

    // ---- section 1: attn copy (CF LDS, coalesced STG) ----
    {
        float* out1 = outb + 128 * 4096;
#pragma unroll
        for (int k = 0; k < 16; k++) {
            const int i = tid + k * THREADS;
            out1[i] = s_a[(i >> 6) * SA_STRIDE + 15 + (i & 63)];
        }
    }

    const float* PB = sm + PB_OFF;
    const float* BB = sm + BB_OFF;

    // ---- branch 0: 1x7 then 7x1 -> section 2 ----
    hbranch<7>(s_a, s_t, PB + 0,   ldpair(BB + 2), h, col0);
    __syncthreads();
    vbranch<7>(s_t, PB + 16,  ldpair(BB + 4), outb + 2 * 128 * 4096, h, col0);
    __syncthreads();

    // ---- branch 1: 1x15 then 15x1 -> section 3 ----
    hbranch<15>(s_a, s_t, PB + 32,  ldpair(BB + 6), h, col0);
    __syncthreads();
    vbranch<15>(s_t, PB + 64,  ldpair(BB + 8), outb + 3 * 128 * 4096, h, col0);
    __syncthreads();

    // ---- branch 2: 1x31 then 31x1 -> section 4 ----
    hbranch<31>(s_a, s_t, PB + 96,  ldpair(BB + 10), h, col0);
    __syncthreads();
    vbranch<31>(s_t, PB + 160, ldpair(BB + 12), outb + 4 * 128 * 4096, h, col0);
}

extern "C" void kernel_launch(void* const* d_in, const int* in_sizes, int n_in,
                              void* d_out, int out_size)
{
    lka_kernel<<<32 * 128, THREADS>>>(
        (const float*)d_in[0],
        (const float*)d_in[1],  (const float*)d_in[2],
        (const float*)d_in[3],  (const float*)d_in[4],
        (const float*)d_in[5],  (const float*)d_in[6],
        (const float*)d_in[7],  (const float*)d_in[8],
        (const float*)d_in[9],  (const float*)d_in[10],
        (const float*)d_in[11], (const float*)d_in[12],
        (const float*)d_in[13], (const float*)d_in[14],
        (float*)d_out);
}